// round 15
// baseline (speedup 1.0000x reference)
#include <cuda_runtime.h>
#include <float.h>

#define NB    4
#define NP    64
#define BP    256           // NB*NP query rows
#define D     768
#define NN    2048
#define RR    12
#define TOPK  16
#define KSPLIT 16           // split-K for out GEMM
#define DSPLIT 8            // split-D for scores GEMM
#define ADJ_BLOCKS 1184

// ---- scratch (static __device__, no allocations) ----
__device__ float g_rnorm[NN];              // 1/||keys_param row||
__device__ float g_spart[DSPLIT][BP * NN]; // scores partials     16.8 MB
__device__ float g_adjsum[NN * NN];        // sum_r adjacency     16.8 MB
__device__ float g_nei[BP * NN];           //                      2.0 MB
__device__ float g_part[KSPLIT][BP * D];   // split-K partials    12.6 MB

#define FMA_F32X2(d, a, b, c) \
    asm("fma.rn.f32x2 %0, %1, %2, %3;" : "=l"(d) : "l"(a), "l"(b), "l"(c))
#define PACK_DUP(d, a) \
    asm("mov.b64 %0, {%1, %1};" : "=l"(d) : "f"(a))

// ---------------------------------------------------------------------------
// K1: fused adj_sum (sum_r adjacency, 201 MB stream) + key inverse norms.
// ---------------------------------------------------------------------------
__global__ void k_adjsum_rnorm(const float* __restrict__ adj,
                               const float* __restrict__ kp) {
    if (blockIdx.x >= ADJ_BLOCKS) {
        int bb = blockIdx.x - ADJ_BLOCKS;
        int w = threadIdx.x >> 5, lane = threadIdx.x & 31;
        for (int rr = 0; rr < 16; rr++) {
            int row = bb * 128 + rr * 8 + w;
            const float* src = kp + (long long)row * D;
            float ss = 0.f;
            #pragma unroll
            for (int i = 0; i < D / 32; i++) { float v = src[i * 32 + lane]; ss += v * v; }
            #pragma unroll
            for (int o = 16; o; o >>= 1) ss += __shfl_xor_sync(0xffffffff, ss, o);
            if (lane == 0) g_rnorm[row] = rsqrtf(ss + 1e-12f);
        }
        return;
    }
    const long long t4 = (long long)NN * NN / 4;
    const long long S = (long long)ADJ_BLOCKS * 256;
    const float4* a = (const float4*)adj;
    float4* o = (float4*)g_adjsum;
    for (long long i = (long long)blockIdx.x * 256 + threadIdx.x; i < t4; i += 2 * S) {
        long long j = i + S;
        bool h2 = j < t4;
        float4 acc0 = __ldcs(&a[i]);
        float4 acc1 = h2 ? __ldcs(&a[j]) : make_float4(0.f, 0.f, 0.f, 0.f);
        #pragma unroll
        for (int r = 1; r < RR; r++) {
            float4 v0 = __ldcs(&a[i + (long long)r * t4]);
            float4 v1 = h2 ? __ldcs(&a[j + (long long)r * t4]) : make_float4(0.f, 0.f, 0.f, 0.f);
            acc0.x += v0.x; acc0.y += v0.y; acc0.z += v0.z; acc0.w += v0.w;
            acc1.x += v1.x; acc1.y += v1.y; acc1.z += v1.z; acc1.w += v1.w;
        }
        o[i] = acc0;
        if (h2) o[j] = acc1;
    }
}

// ---------------------------------------------------------------------------
// K2: spart[z][m,n] = sum_{d in z-chunk} pos[m,d]*kp[n,d]*rnorm[n]  (NT)
// 64x64 tile, BK=16, 256 thr, 4x4 thread tile, f32x2 reg dup-pack,
// double-buffered smem (1 barrier/tile), LDG reg prefetch.
// ---------------------------------------------------------------------------
__global__ __launch_bounds__(256, 4)
void k_scores(const float* __restrict__ pos, const float* __restrict__ kp) {
    __shared__ float As[2][16][68];
    __shared__ float Bs[2][16][68];
    int n0 = blockIdx.x * 64, m0 = blockIdx.y * 64;
    int z = blockIdx.z;
    int t = threadIdx.x;
    int tx = t & 15, ty = t >> 4;        // tx: n-quad, ty: m-quad
    int am = t >> 2, aq = t & 3;         // loader: row am, k-quad aq
    const int KCH = D / DSPLIT, NIT = KCH / 16;
    int kb = z * KCH;
    float brn = g_rnorm[n0 + am];

    float4 aP, bP;
    aP = *(const float4*)&pos[(long long)(m0 + am) * D + kb + aq * 4];
    bP = *(const float4*)&kp[(long long)(n0 + am) * D + kb + aq * 4];
    As[0][aq * 4 + 0][am] = aP.x;
    As[0][aq * 4 + 1][am] = aP.y;
    As[0][aq * 4 + 2][am] = aP.z;
    As[0][aq * 4 + 3][am] = aP.w;
    Bs[0][aq * 4 + 0][am] = bP.x * brn;
    Bs[0][aq * 4 + 1][am] = bP.y * brn;
    Bs[0][aq * 4 + 2][am] = bP.z * brn;
    Bs[0][aq * 4 + 3][am] = bP.w * brn;
    __syncthreads();

    unsigned long long acc[4][2] = {};
    int p = 0;
    for (int it = 0; it < NIT; it++) {
        if (it + 1 < NIT) {
            int k0 = kb + (it + 1) * 16;
            aP = *(const float4*)&pos[(long long)(m0 + am) * D + k0 + aq * 4];
            bP = *(const float4*)&kp[(long long)(n0 + am) * D + k0 + aq * 4];
        }
        #pragma unroll
        for (int kk = 0; kk < 16; kk++) {
            float4 af = *(const float4*)&As[p][kk][ty * 4];
            ulonglong2 bb = *(const ulonglong2*)&Bs[p][kk][tx * 4];
            unsigned long long a0, a1, a2, a3;
            PACK_DUP(a0, af.x); PACK_DUP(a1, af.y);
            PACK_DUP(a2, af.z); PACK_DUP(a3, af.w);
            FMA_F32X2(acc[0][0], a0, bb.x, acc[0][0]);
            FMA_F32X2(acc[0][1], a0, bb.y, acc[0][1]);
            FMA_F32X2(acc[1][0], a1, bb.x, acc[1][0]);
            FMA_F32X2(acc[1][1], a1, bb.y, acc[1][1]);
            FMA_F32X2(acc[2][0], a2, bb.x, acc[2][0]);
            FMA_F32X2(acc[2][1], a2, bb.y, acc[2][1]);
            FMA_F32X2(acc[3][0], a3, bb.x, acc[3][0]);
            FMA_F32X2(acc[3][1], a3, bb.y, acc[3][1]);
        }
        if (it + 1 < NIT) {
            int pn = p ^ 1;
            As[pn][aq * 4 + 0][am] = aP.x;
            As[pn][aq * 4 + 1][am] = aP.y;
            As[pn][aq * 4 + 2][am] = aP.z;
            As[pn][aq * 4 + 3][am] = aP.w;
            Bs[pn][aq * 4 + 0][am] = bP.x * brn;
            Bs[pn][aq * 4 + 1][am] = bP.y * brn;
            Bs[pn][aq * 4 + 2][am] = bP.z * brn;
            Bs[pn][aq * 4 + 3][am] = bP.w * brn;
        }
        __syncthreads();
        p ^= 1;
    }
    #pragma unroll
    for (int mm = 0; mm < 4; mm++) {
        float2 lo = *(float2*)&acc[mm][0];
        float2 hi = *(float2*)&acc[mm][1];
        float4 o = {lo.x, lo.y, hi.x, hi.y};
        *(float4*)&g_spart[z][(long long)(m0 + ty * 4 + mm) * NN + n0 + tx * 4] = o;
    }
}

// ---------------------------------------------------------------------------
// K3: fused (scores partial sum) + top-16 + softmax + nei gather.
// Block per row, 512 threads.
// ---------------------------------------------------------------------------
__global__ void k_topknei() {
    int row = blockIdx.x;
    int w = threadIdx.x >> 5, lane = threadIdx.x & 31;
    int tid = threadIdx.x;
    __shared__ float cv[8][TOPK];
    __shared__ int   ci[8][TOPK];
    __shared__ float swgt[TOPK];
    __shared__ int   sid[TOPK];
    __shared__ float rv_[TOPK];

    if (w < 8) {
        float4 x = {0.f, 0.f, 0.f, 0.f}, y = {0.f, 0.f, 0.f, 0.f};
        #pragma unroll
        for (int z = 0; z < DSPLIT; z++) {
            const float4* p = (const float4*)(g_spart[z] + (long long)row * NN);
            float4 xa = p[w * 64 + lane];
            float4 ya = p[w * 64 + 32 + lane];
            x.x += xa.x; x.y += xa.y; x.z += xa.z; x.w += xa.w;
            y.x += ya.x; y.y += ya.y; y.z += ya.z; y.w += ya.w;
        }
        int b0 = (w * 64 + lane) * 4, b1 = (w * 64 + 32 + lane) * 4;
        float v[8]  = {x.x, x.y, x.z, x.w, y.x, y.y, y.z, y.w};
        int   id[8] = {b0, b0 + 1, b0 + 2, b0 + 3, b1, b1 + 1, b1 + 2, b1 + 3};

        // descending sort, tie -> smaller index (19-CE Batcher network)
        #define CE(i, j) do {                                                 \
            float _av = v[i], _bv = v[j]; int _ai = id[i], _bi = id[j];       \
            bool _sw = (_bv > _av) || (_bv == _av && _bi < _ai);              \
            v[i]  = _sw ? _bv : _av;  id[i] = _sw ? _bi : _ai;                \
            v[j]  = _sw ? _av : _bv;  id[j] = _sw ? _ai : _bi;                \
        } while (0)
        CE(0,1); CE(2,3); CE(4,5); CE(6,7);
        CE(0,2); CE(1,3); CE(4,6); CE(5,7);
        CE(1,2); CE(5,6);
        CE(0,4); CE(1,5); CE(2,6); CE(3,7);
        CE(2,4); CE(3,5);
        CE(1,2); CE(3,4); CE(5,6);
        #undef CE

        #pragma unroll 1
        for (int r = 0; r < TOPK; r++) {
            float wv = v[0]; int wi = id[0];
            #pragma unroll
            for (int o = 16; o; o >>= 1) {
                float ov = __shfl_xor_sync(0xffffffff, wv, o);
                int   oi = __shfl_xor_sync(0xffffffff, wi, o);
                if (ov > wv || (ov == wv && oi < wi)) { wv = ov; wi = oi; }
            }
            if (wi == id[0]) {
                #pragma unroll
                for (int q = 0; q < 7; q++) { v[q] = v[q + 1]; id[q] = id[q + 1]; }
                v[7] = -FLT_MAX; id[7] = 1 << 30;
            }
            if (lane == 0) { cv[w][r] = wv; ci[w][r] = wi; }
        }
    }
    __syncthreads();

    if (w == 0) {
        int p = 0;
        #pragma unroll 1
        for (int r = 0; r < TOPK; r++) {
            float hv = (lane < 8) ? cv[lane][p] : -FLT_MAX;
            int   hi = (lane < 8) ? ci[lane][p] : (1 << 30);
            float wv = hv; int wi = hi;
            #pragma unroll
            for (int o = 16; o; o >>= 1) {
                float ov = __shfl_xor_sync(0xffffffff, wv, o);
                int   oi = __shfl_xor_sync(0xffffffff, wi, o);
                if (ov > wv || (ov == wv && oi < wi)) { wv = ov; wi = oi; }
            }
            if (lane < 8 && wi == hi) p++;
            if (lane == 0) { rv_[r] = wv; sid[r] = wi; }
        }
        __syncwarp();
        if (lane < TOPK) {
            float e = expf(rv_[lane] - rv_[0]);
            float sum = e;
            #pragma unroll
            for (int o = 1; o < TOPK; o <<= 1)
                sum += __shfl_xor_sync(0xffff, sum, o);
            swgt[lane] = e / sum;
        }
    }
    __syncthreads();

    float wgt[TOPK]; int idn[TOPK];
    #pragma unroll
    for (int k = 0; k < TOPK; k++) { wgt[k] = swgt[k]; idn[k] = sid[k]; }
    const float4* a4 = (const float4*)g_adjsum;
    float4 acc = {0.f, 0.f, 0.f, 0.f};
    #pragma unroll
    for (int k = 0; k < TOPK; k++) {
        float4 vv = a4[(long long)idn[k] * (NN / 4) + tid];
        float wk = wgt[k];
        acc.x += wk * vv.x; acc.y += wk * vv.y; acc.z += wk * vv.z; acc.w += wk * vv.w;
    }
    ((float4*)g_nei)[(long long)row * (NN / 4) + tid] = acc;
}

// ---------------------------------------------------------------------------
// K4: partial[z][m,d] = sum_{n in z-chunk} nei[m,n]*kp[n,d]*rnorm[n]
// 64x64 tile, BK=16, 4x4 thread tile, f32x2 reg dup-pack, double buffer.
// ---------------------------------------------------------------------------
__global__ __launch_bounds__(256, 4)
void k_out_part(const float* __restrict__ kp) {
    __shared__ float As[2][16][68];
    __shared__ float Bs[2][16][68];
    int d0 = blockIdx.x * 64, m0 = blockIdx.y * 64;
    int kz = blockIdx.z;
    int t = threadIdx.x;
    int tx = t & 15, ty = t >> 4;        // tx: d-quad, ty: m-quad
    int am = t >> 2, aq = t & 3;         // A loader: row am, k-quad aq
    int bk = t >> 4, bq = t & 15;        // B loader: k-row bk, d-quad bq
    const int KCH = NN / KSPLIT, NIT = KCH / 16;
    int kb = kz * KCH;

    float4 aP, bP; float brnP;
    aP   = *(const float4*)&g_nei[(long long)(m0 + am) * NN + kb + aq * 4];
    brnP = g_rnorm[kb + bk];
    bP   = *(const float4*)&kp[(long long)(kb + bk) * D + d0 + bq * 4];
    {
        As[0][aq * 4 + 0][am] = aP.x;
        As[0][aq * 4 + 1][am] = aP.y;
        As[0][aq * 4 + 2][am] = aP.z;
        As[0][aq * 4 + 3][am] = aP.w;
        float4 bv = bP;
        bv.x *= brnP; bv.y *= brnP; bv.z *= brnP; bv.w *= brnP;
        *(float4*)&Bs[0][bk][bq * 4] = bv;
    }
    __syncthreads();

    unsigned long long acc[4][2] = {};
    int p = 0;
    for (int it = 0; it < NIT; it++) {
        if (it + 1 < NIT) {
            int k0 = kb + (it + 1) * 16;
            aP   = *(const float4*)&g_nei[(long long)(m0 + am) * NN + k0 + aq * 4];
            brnP = g_rnorm[k0 + bk];
            bP   = *(const float4*)&kp[(long long)(k0 + bk) * D + d0 + bq * 4];
        }
        #pragma unroll
        for (int kk = 0; kk < 16; kk++) {
            float4 af = *(const float4*)&As[p][kk][ty * 4];
            ulonglong2 bb = *(const ulonglong2*)&Bs[p][kk][tx * 4];
            unsigned long long a0, a1, a2, a3;
            PACK_DUP(a0, af.x); PACK_DUP(a1, af.y);
            PACK_DUP(a2, af.z); PACK_DUP(a3, af.w);
            FMA_F32X2(acc[0][0], a0, bb.x, acc[0][0]);
            FMA_F32X2(acc[0][1], a0, bb.y, acc[0][1]);
            FMA_F32X2(acc[1][0], a1, bb.x, acc[1][0]);
            FMA_F32X2(acc[1][1], a1, bb.y, acc[1][1]);
            FMA_F32X2(acc[2][0], a2, bb.x, acc[2][0]);
            FMA_F32X2(acc[2][1], a2, bb.y, acc[2][1]);
            FMA_F32X2(acc[3][0], a3, bb.x, acc[3][0]);
            FMA_F32X2(acc[3][1], a3, bb.y, acc[3][1]);
        }
        if (it + 1 < NIT) {
            int pn = p ^ 1;
            As[pn][aq * 4 + 0][am] = aP.x;
            As[pn][aq * 4 + 1][am] = aP.y;
            As[pn][aq * 4 + 2][am] = aP.z;
            As[pn][aq * 4 + 3][am] = aP.w;
            float4 bv = bP;
            bv.x *= brnP; bv.y *= brnP; bv.z *= brnP; bv.w *= brnP;
            *(float4*)&Bs[pn][bk][bq * 4] = bv;
        }
        __syncthreads();
        p ^= 1;
    }
    #pragma unroll
    for (int mm = 0; mm < 4; mm++) {
        float2 lo = *(float2*)&acc[mm][0];
        float2 hi = *(float2*)&acc[mm][1];
        float4 o = {lo.x, lo.y, hi.x, hi.y};
        *(float4*)&g_part[kz][(long long)(m0 + ty * 4 + mm) * D + d0 + tx * 4] = o;
    }
}

// K5: out = sum_z partial[z]
__global__ void k_reduce(float* __restrict__ out) {
    int i = blockIdx.x * blockDim.x + threadIdx.x;     // 49152 float4
    float4 acc = {0.f, 0.f, 0.f, 0.f};
    #pragma unroll
    for (int z = 0; z < KSPLIT; z++) {
        float4 v = ((const float4*)g_part[z])[i];
        acc.x += v.x; acc.y += v.y; acc.z += v.z; acc.w += v.w;
    }
    ((float4*)out)[i] = acc;
}

// ---------------------------------------------------------------------------
extern "C" void kernel_launch(void* const* d_in, const int* in_sizes, int n_in,
                              void* d_out, int out_size) {
    const float* pos = (const float*)d_in[0];   // (4,64,768) f32
    const float* kp  = (const float*)d_in[1];   // (2048,768) f32
    const float* adj = (const float*)d_in[2];   // (12,2048,2048) f32
    float* out = (float*)d_out;                 // (4,64,768) f32

    k_adjsum_rnorm<<<ADJ_BLOCKS + 16, 256>>>(adj, kp);
    k_scores<<<dim3(NN / 64, BP / 64, DSPLIT), 256>>>(pos, kp);
    k_topknei<<<BP, 512>>>();
    k_out_part<<<dim3(D / 64, BP / 64, KSPLIT), 256>>>(kp);
    k_reduce<<<BP * D / 4 / 256, 256>>>(out);
}